// round 16
// baseline (speedup 1.0000x reference)
#include <cuda_runtime.h>
#include <cuda_fp16.h>
#include <math.h>
#include <cstdint>
#include <cstddef>

// ---------------- problem constants ----------------
#define T_TOK   2048
#define DIMX    2048
#define QKVC    3072      // (32 + 2*8) * 64
#define NKV     8
#define WIN     128
#define TQ      16

// Scratch (no allocs allowed)
__device__ float  g_qkv[(size_t)T_TOK * QKVC];        // fp32 qkv (rope in-place)
__device__ __half g_attn_h[(size_t)T_TOK * DIMX];     // fp16 attention output
__device__ __half g_xh[(size_t)T_TOK * DIMX];         // fp16 x
__device__ __half g_wqkvh[(size_t)QKVC * DIMX];       // fp16 Wqkv
__device__ __half g_woh[(size_t)DIMX * DIMX];         // fp16 Wo

// ---------------- helpers ----------------
__device__ __forceinline__ uint32_t smem_u32(const void* p) {
    uint32_t a;
    asm("{ .reg .u64 t; cvta.to.shared.u64 t, %1; cvt.u32.u64 %0, t; }"
        : "=r"(a) : "l"(p));
    return a;
}
__device__ __forceinline__ float f2tf32f(float f) {
    uint32_t r;
    asm("cvt.rna.tf32.f32 %0, %1;" : "=r"(r) : "f"(f));
    return __uint_as_float(r);
}
__device__ __forceinline__ void mma_tf32(float* d, const uint32_t* a,
                                         const uint32_t* b) {
    asm volatile(
        "mma.sync.aligned.m16n8k8.row.col.f32.tf32.tf32.f32 "
        "{%0,%1,%2,%3}, {%4,%5,%6,%7}, {%8,%9}, {%0,%1,%2,%3};"
        : "+f"(d[0]), "+f"(d[1]), "+f"(d[2]), "+f"(d[3])
        : "r"(a[0]), "r"(a[1]), "r"(a[2]), "r"(a[3]), "r"(b[0]), "r"(b[1]));
}
__device__ __forceinline__ void mma_f16(float* d, const uint32_t* a,
                                        uint32_t b0, uint32_t b1) {
    asm volatile(
        "mma.sync.aligned.m16n8k16.row.col.f32.f16.f16.f32 "
        "{%0,%1,%2,%3}, {%4,%5,%6,%7}, {%8,%9}, {%0,%1,%2,%3};"
        : "+f"(d[0]), "+f"(d[1]), "+f"(d[2]), "+f"(d[3])
        : "r"(a[0]), "r"(a[1]), "r"(a[2]), "r"(a[3]), "r"(b0), "r"(b1));
}
__device__ __forceinline__ void ldsm_x4(uint32_t* r, uint32_t addr) {
    asm volatile(
        "ldmatrix.sync.aligned.m8n8.x4.shared.b16 {%0,%1,%2,%3}, [%4];"
        : "=r"(r[0]), "=r"(r[1]), "=r"(r[2]), "=r"(r[3]) : "r"(addr));
}

// ---------------- fp32 -> fp16 pre-convert pass ----------------
__global__ void cvt_f16_kernel(const float* __restrict__ in,
                               __half* __restrict__ out, int n4)
{
    int i = blockIdx.x * blockDim.x + threadIdx.x;
    if (i < n4) {
        float4 v = *(const float4*)(in + (size_t)i * 4);
        __half2 h0 = __floats2half2_rn(v.x, v.y);
        __half2 h1 = __floats2half2_rn(v.z, v.w);
        ((__half2*)out)[2 * i]     = h0;
        ((__half2*)out)[2 * i + 1] = h1;
    }
}

// ---------------- fp16 mma.sync GEMM (m16n8k16, static copy map) ------------
// C[M, Ntot] = A[M, K] * B[Ntot, K]^T + bias.  A, B are fp16, C fp32.
// CTA tile 128 x (16*NT), BK=32 halves, 3-stage cp.async, 256 threads,
// warp grid 4M x 2N.  PADH=40 halves (80 B row stride, odd x16B -> LDSM-clean).
#define GBM  128
#define PADH 40

template <int NT>
__global__ __launch_bounds__(256, 2)
void gemm_mma_f16(const __half* __restrict__ A, const __half* __restrict__ B,
                  const float* __restrict__ bias, float* __restrict__ C,
                  int Ntot, int K)
{
    constexpr int BN   = NT * 16;
    constexpr int ROWS = GBM + BN;
    constexpr int STGB = ROWS * PADH * 2;     // bytes per stage

    extern __shared__ char smc[];
    const uint32_t sbase = smem_u32(smc);

    const int tid  = threadIdx.x;
    const int lane = tid & 31;
    const int wid  = tid >> 5;
    const int warpM = wid & 3;
    const int warpN = wid >> 2;
    const int gid = lane >> 2;
    const int tig = lane & 3;

    const int m0 = blockIdx.y * GBM;
    const int n0 = blockIdx.x * BN;
    const int niter = K / 32;

    // ---- static copy mapping (computed once) ----
    const int crow = tid >> 1;               // 0..127
    const int ccol = (tid & 1) * 16;         // halves: 0 or 16
    const char* srcA = (const char*)(A + (size_t)(m0 + crow) * K + ccol);
    const char* srcB = (const char*)(B + (size_t)(n0 + (crow < BN ? crow : 0)) * K + ccol);
    const bool  doB  = (NT == 8) ? true : (tid < 2 * BN);
    const uint32_t dstA = (uint32_t)(crow * PADH * 2 + ccol * 2);
    const uint32_t dstB = (uint32_t)((GBM + crow) * PADH * 2 + ccol * 2);

    // ldmatrix per-lane: tile order (r0-7,kLo),(r8-15,kLo),(r0-7,kHi),(r8-15,kHi)
    const int q    = lane >> 3;
    const int row8 = ((q & 1) << 3) + (lane & 7);
    const int kofB = (q >> 1) << 4;                 // 0 or 16 bytes
    const uint32_t a_off = (uint32_t)((warpM * 32 + row8) * PADH * 2 + kofB);
    const uint32_t b_off = (uint32_t)((GBM + warpN * NT * 8 + row8) * PADH * 2 + kofB);

    float acc[2][NT][4];
#pragma unroll
    for (int mt = 0; mt < 2; mt++)
#pragma unroll
        for (int nt = 0; nt < NT; nt++)
#pragma unroll
            for (int z = 0; z < 4; z++) acc[mt][nt][z] = 0.f;

    auto issue = [&](int kt, int s) {
        if (kt < niter) {
            const char* a = srcA + (size_t)kt * 64;   // 32 halves = 64 B
            uint32_t da = sbase + (uint32_t)s * STGB + dstA;
            asm volatile("cp.async.cg.shared.global [%0], [%1], 16;"
                         :: "r"(da), "l"(a) : "memory");
            asm volatile("cp.async.cg.shared.global [%0], [%1], 16;"
                         :: "r"(da + 16), "l"(a + 16) : "memory");
            if (doB) {
                const char* b = srcB + (size_t)kt * 64;
                uint32_t db = sbase + (uint32_t)s * STGB + dstB;
                asm volatile("cp.async.cg.shared.global [%0], [%1], 16;"
                             :: "r"(db), "l"(b) : "memory");
                asm volatile("cp.async.cg.shared.global [%0], [%1], 16;"
                             :: "r"(db + 16), "l"(b + 16) : "memory");
            }
        }
        asm volatile("cp.async.commit_group;" ::: "memory");
    };

    issue(0, 0);
    issue(1, 1);

    for (int it = 0; it < niter; it++) {
        asm volatile("cp.async.wait_group 1;" ::: "memory");
        __syncthreads();
        issue(it + 2, (it + 2) % 3);

        const uint32_t stg = sbase + (uint32_t)((it % 3) * STGB);
        const uint32_t aB = stg + a_off;
        const uint32_t bB = stg + b_off;

#pragma unroll
        for (int ks = 0; ks < 2; ks++) {            // two k16 steps per BK=32
            const uint32_t kb = ks * 32;            // 16 halves = 32 bytes
            uint32_t afr[2][4];
            ldsm_x4(afr[0], aB + kb);
            ldsm_x4(afr[1], aB + kb + 16 * PADH * 2);
            uint32_t bfr[NT / 2][4];
#pragma unroll
            for (int p = 0; p < NT / 2; p++)
                ldsm_x4(bfr[p], bB + kb + (uint32_t)(p * 16 * PADH * 2));
#pragma unroll
            for (int mt = 0; mt < 2; mt++)
#pragma unroll
                for (int p = 0; p < NT / 2; p++) {
                    mma_f16(acc[mt][2 * p + 0], afr[mt], bfr[p][0], bfr[p][2]);
                    mma_f16(acc[mt][2 * p + 1], afr[mt], bfr[p][1], bfr[p][3]);
                }
        }
    }

    // ---- epilogue: bias (fp32 out) ----
#pragma unroll
    for (int mt = 0; mt < 2; mt++) {
        int row = m0 + warpM * 32 + mt * 16 + gid;
#pragma unroll
        for (int nt = 0; nt < NT; nt++) {
            int col = n0 + warpN * NT * 8 + nt * 8 + 2 * tig;
            float b0 = __ldg(&bias[col]);
            float b1 = __ldg(&bias[col + 1]);
            *(float2*)(C + (size_t)row * Ntot + col) =
                make_float2(acc[mt][nt][0] + b0, acc[mt][nt][1] + b1);
            *(float2*)(C + (size_t)(row + 8) * Ntot + col) =
                make_float2(acc[mt][nt][2] + b0, acc[mt][nt][3] + b1);
        }
    }
}

// padded to force exactly 2 CTAs/SM on the NT6 grid
#define GEMM_SMEM_NT6 98304
#define GEMM_SMEM_NT8 ((GBM + 128) * PADH * 2 * 3)   // 61440

// ---------------- RoPE (standalone, frozen) ----------------
__global__ void rope_kernel(const float* __restrict__ cosT,
                            const float* __restrict__ sinT)
{
    const int t = blockIdx.x;
    float* row = g_qkv + (size_t)t * QKVC;
    const float* ct = cosT + t * 64;
    const float* st = sinT + t * 64;
    for (int p = threadIdx.x; p < 40 * 32; p += blockDim.x) {
        int hh = p >> 5;
        int dl = p & 31;
        int base = (hh < 32) ? hh * 64 : 2048 + (hh - 32) * 64;
        float lo = row[base + dl];
        float hi = row[base + dl + 32];
        float c0 = ct[dl],      s0 = st[dl];
        float c1 = ct[dl + 32], s1 = st[dl + 32];
        row[base + dl]      = lo * c0 - hi * s0;
        row[base + dl + 32] = hi * c1 + lo * s1;
    }
}

// ---------------- SWA v3 (frozen; fp16 output) ----------------
#define SQ_STR 68
#define SK_STR 68
#define SP_STR 164
#define SV_STR 164
#define NU     160
#define OFF_Q   0
#define OFF_K   4352
#define OFF_P   OFF_K
#define OFF_V   15232
#define OFF_DEN 25728
#define SWA_SMEM ((25728 + 64) * 4)     // 103168 bytes -> 2 CTAs/SM

__global__ __launch_bounds__(256, 2)
void swa_kernel(const float* __restrict__ sinks)
{
    extern __shared__ float sm[];
    const uint32_t sb = smem_u32(sm);
    const int tid = threadIdx.x, lane = tid & 31, wid = tid >> 5;
    const int gid = lane >> 2, tig = lane & 3;
    const int t0  = blockIdx.x * TQ;
    const int kvh = blockIdx.y;

    float* Qs  = sm + OFF_Q;
    float* Ks  = sm + OFF_K;
    float* Vt  = sm + OFF_V;
    float* P   = sm + OFF_P;
    float* den = sm + OFF_DEN;

    for (int idx = tid; idx < NU * 64; idx += 256) {
        int u = idx >> 6, d = idx & 63;
        int j = t0 - 127 + u;
        float kv = 0.f, vv = 0.f;
        if (u <= 142 && j >= 0) {
            const float* r = g_qkv + (size_t)j * QKVC;
            kv = f2tf32f(r[2048 + kvh * 64 + d]);
            vv = f2tf32f(r[2560 + kvh * 64 + d]);
        }
        Ks[u * SK_STR + d] = kv;
        Vt[d * SV_STR + u] = vv;
    }
    for (int idx = tid; idx < 64 * 64; idx += 256) {
        int r = idx >> 6, d = idx & 63;
        int i = r >> 2, g = r & 3;
        Qs[r * SQ_STR + d] = f2tf32f(
            g_qkv[(size_t)(t0 + i) * QKVC + (kvh * 4 + g) * 64 + d] * 0.125f);
    }
    __syncthreads();

    const int q = lane >> 3;
    const int arow = ((q & 1) << 3) + (lane & 7);
    const int akof = (q >> 1) << 2;
    const int brow = ((q >> 1) << 3) + (lane & 7);
    const int bkof = (q & 1) << 2;

    {
        const int mrow = (wid & 3) << 4;
        const int ncol = (wid >> 2) * 80;
        float s[10][4];
#pragma unroll
        for (int nt = 0; nt < 10; nt++)
#pragma unroll
            for (int z = 0; z < 4; z++) s[nt][z] = 0.f;

        const uint32_t Qb = sb + (uint32_t)((OFF_Q + (mrow + arow) * SQ_STR + akof) * 4);
        const uint32_t Kb = sb + (uint32_t)((OFF_K + (ncol + brow) * SK_STR + bkof) * 4);
#pragma unroll
        for (int ks = 0; ks < 8; ks++) {
            const uint32_t kb = ks * 32;
            uint32_t afr[4];
            ldsm_x4(afr, Qb + kb);
            uint32_t bfr[5][4];
#pragma unroll
            for (int p = 0; p < 5; p++)
                ldsm_x4(bfr[p], Kb + kb + (uint32_t)(p * 16 * SK_STR * 4));
#pragma unroll
            for (int p = 0; p < 5; p++) {
                mma_tf32(s[2 * p + 0], afr, &bfr[p][0]);
                mma_tf32(s[2 * p + 1], afr, &bfr[p][2]);
            }
        }
        __syncthreads();
#pragma unroll
        for (int nt = 0; nt < 10; nt++) {
            int col = ncol + nt * 8 + 2 * tig;
            P[(mrow + gid) * SP_STR + col]         = s[nt][0];
            P[(mrow + gid) * SP_STR + col + 1]     = s[nt][1];
            P[(mrow + gid + 8) * SP_STR + col]     = s[nt][2];
            P[(mrow + gid + 8) * SP_STR + col + 1] = s[nt][3];
        }
    }
    __syncthreads();

    {
        const int lim = 127 - t0;
        for (int rr = 0; rr < 8; rr++) {
            int r = wid * 8 + rr;
            int i = r >> 2, g = r & 3;
            int lo = (i > lim) ? i : lim;
            int hi = i + 127;
            float v[5];
#pragma unroll
            for (int c = 0; c < 5; c++) {
                int u = lane + c * 32;
                float x = P[r * SP_STR + u];
                v[c] = (u >= lo && u <= hi) ? x : -1e30f;
            }
            float m = v[0];
#pragma unroll
            for (int c = 1; c < 5; c++) m = fmaxf(m, v[c]);
#pragma unroll
            for (int o = 16; o; o >>= 1)
                m = fmaxf(m, __shfl_xor_sync(0xffffffffu, m, o));
            float snk = __ldg(&sinks[kvh * 4 + g]);
            m = fmaxf(m, snk);
            float sum = 0.f;
#pragma unroll
            for (int c = 0; c < 5; c++) {
                int u = lane + c * 32;
                float e = 0.f;
                if (u >= lo && u <= hi) e = f2tf32f(__expf(v[c] - m));
                P[r * SP_STR + u] = e;
                sum += e;
            }
#pragma unroll
            for (int o = 16; o; o >>= 1)
                sum += __shfl_xor_sync(0xffffffffu, sum, o);
            sum += __expf(snk - m);
            if (lane == 0) den[r] = 1.0f / sum;
        }
    }
    __syncthreads();

    {
        const int mrow = (wid & 3) << 4;
        const int ncol = (wid >> 2) << 5;
        float o[4][4];
#pragma unroll
        for (int nt = 0; nt < 4; nt++)
#pragma unroll
            for (int z = 0; z < 4; z++) o[nt][z] = 0.f;

        const uint32_t Pb = sb + (uint32_t)((OFF_P + (mrow + arow) * SP_STR + akof) * 4);
        const uint32_t Vb = sb + (uint32_t)((OFF_V + (ncol + brow) * SV_STR + bkof) * 4);
#pragma unroll
        for (int ks = 0; ks < 20; ks++) {
            const uint32_t kb = ks * 32;
            uint32_t afr[4];
            ldsm_x4(afr, Pb + kb);
            uint32_t bfr[2][4];
            ldsm_x4(bfr[0], Vb + kb);
            ldsm_x4(bfr[1], Vb + kb + (uint32_t)(16 * SV_STR * 4));
#pragma unroll
            for (int p = 0; p < 2; p++) {
                mma_tf32(o[2 * p + 0], afr, &bfr[p][0]);
                mma_tf32(o[2 * p + 1], afr, &bfr[p][2]);
            }
        }
        int r0 = mrow + gid, r1 = r0 + 8;
        float i0 = den[r0], i1 = den[r1];
        int tA = t0 + (r0 >> 2), chA = (kvh * 4 + (r0 & 3)) * 64;
        int tB = t0 + (r1 >> 2), chB = (kvh * 4 + (r1 & 3)) * 64;
#pragma unroll
        for (int nt = 0; nt < 4; nt++) {
            int col = ncol + nt * 8 + 2 * tig;
            *(__half2*)(g_attn_h + (size_t)tA * DIMX + chA + col) =
                __floats2half2_rn(o[nt][0] * i0, o[nt][1] * i0);
            *(__half2*)(g_attn_h + (size_t)tB * DIMX + chB + col) =
                __floats2half2_rn(o[nt][2] * i1, o[nt][3] * i1);
        }
    }
}

// ---------------- host ----------------
extern "C" void kernel_launch(void* const* d_in, const int* in_sizes, int n_in,
                              void* d_out, int out_size)
{
    (void)in_sizes; (void)n_in; (void)out_size;
    const float* x     = (const float*)d_in[0];
    const float* cosT  = (const float*)d_in[1];
    const float* sinT  = (const float*)d_in[2];
    const float* Wqkv  = (const float*)d_in[3];
    const float* bqkv  = (const float*)d_in[4];
    const float* Wo    = (const float*)d_in[5];
    const float* bo    = (const float*)d_in[6];
    const float* sinks = (const float*)d_in[7];
    float* out = (float*)d_out;

    float*  qkv = nullptr;
    __half *xh = nullptr, *wqkvh = nullptr, *woh = nullptr, *attnh = nullptr;
    cudaGetSymbolAddress((void**)&qkv,   g_qkv);
    cudaGetSymbolAddress((void**)&xh,    g_xh);
    cudaGetSymbolAddress((void**)&wqkvh, g_wqkvh);
    cudaGetSymbolAddress((void**)&woh,   g_woh);
    cudaGetSymbolAddress((void**)&attnh, g_attn_h);

    cudaFuncSetAttribute((const void*)gemm_mma_f16<6>,
                         cudaFuncAttributeMaxDynamicSharedMemorySize, GEMM_SMEM_NT6);
    cudaFuncSetAttribute((const void*)gemm_mma_f16<8>,
                         cudaFuncAttributeMaxDynamicSharedMemorySize, GEMM_SMEM_NT8);
    cudaFuncSetAttribute(swa_kernel,
                         cudaFuncAttributeMaxDynamicSharedMemorySize, SWA_SMEM);

    // 0) fp32 -> fp16 pre-convert passes
    cvt_f16_kernel<<<(T_TOK * DIMX / 4 + 255) / 256, 256>>>(x,    xh,    T_TOK * DIMX / 4);
    cvt_f16_kernel<<<(QKVC * DIMX / 4 + 255) / 256, 256>>>(Wqkv, wqkvh, QKVC * DIMX / 4);
    cvt_f16_kernel<<<(DIMX * DIMX / 4 + 255) / 256, 256>>>(Wo,   woh,   DIMX * DIMX / 4);

    // 1) qkv = x @ Wqkv^T + bqkv  (fp16 mma, BN=96 -> 512 CTAs, 2 CTAs/SM)
    gemm_mma_f16<6><<<dim3(QKVC / 96, T_TOK / GBM), 256, GEMM_SMEM_NT6>>>(
        xh, wqkvh, bqkv, qkv, QKVC, DIMX);
    // 2) RoPE in-place on q,k (fp32)
    rope_kernel<<<T_TOK, 256>>>(cosT, sinT);
    // 3) tensorized sliding-window attention with sink (2 CTAs/SM, fp16 out)
    swa_kernel<<<dim3(T_TOK / TQ, NKV), 256, SWA_SMEM>>>(sinks);
    // 4) out = attn @ Wo^T + bo   (fp16 mma, BN=128 -> 256 CTAs)
    gemm_mma_f16<8><<<dim3(DIMX / 128, T_TOK / GBM), 256, GEMM_SMEM_NT8>>>(
        attnh, woh, bo, out, DIMX, DIMX);
}

// round 17
// speedup vs baseline: 1.1229x; 1.1229x over previous
#include <cuda_runtime.h>
#include <cuda_fp16.h>
#include <math.h>
#include <cstdint>
#include <cstddef>

// ---------------- problem constants ----------------
#define T_TOK   2048
#define DIMX    2048
#define QKVC    3072      // (32 + 2*8) * 64
#define NKV     8
#define WIN     128
#define TQ      16

// Scratch (no allocs allowed)
__device__ float  g_qkv[(size_t)T_TOK * QKVC];        // fp32 qkv (rope in-place)
__device__ __half g_attn_h[(size_t)T_TOK * DIMX];     // fp16 attention output
__device__ __half g_xh[(size_t)T_TOK * DIMX];         // fp16 x
__device__ __half g_wqkvh[(size_t)QKVC * DIMX];       // fp16 Wqkv
__device__ __half g_woh[(size_t)DIMX * DIMX];         // fp16 Wo

// ---------------- helpers ----------------
__device__ __forceinline__ uint32_t smem_u32(const void* p) {
    uint32_t a;
    asm("{ .reg .u64 t; cvta.to.shared.u64 t, %1; cvt.u32.u64 %0, t; }"
        : "=r"(a) : "l"(p));
    return a;
}
__device__ __forceinline__ void mma_f16(float* d, const uint32_t* a,
                                        uint32_t b0, uint32_t b1) {
    asm volatile(
        "mma.sync.aligned.m16n8k16.row.col.f32.f16.f16.f32 "
        "{%0,%1,%2,%3}, {%4,%5,%6,%7}, {%8,%9}, {%0,%1,%2,%3};"
        : "+f"(d[0]), "+f"(d[1]), "+f"(d[2]), "+f"(d[3])
        : "r"(a[0]), "r"(a[1]), "r"(a[2]), "r"(a[3]), "r"(b0), "r"(b1));
}
__device__ __forceinline__ void ldsm_x4(uint32_t* r, uint32_t addr) {
    asm volatile(
        "ldmatrix.sync.aligned.m8n8.x4.shared.b16 {%0,%1,%2,%3}, [%4];"
        : "=r"(r[0]), "=r"(r[1]), "=r"(r[2]), "=r"(r[3]) : "r"(addr));
}

// ---------------- fp32 -> fp16 pre-convert pass ----------------
__global__ void cvt_f16_kernel(const float* __restrict__ in,
                               __half* __restrict__ out, int n4)
{
    int i = blockIdx.x * blockDim.x + threadIdx.x;
    if (i < n4) {
        float4 v = *(const float4*)(in + (size_t)i * 4);
        __half2 h0 = __floats2half2_rn(v.x, v.y);
        __half2 h1 = __floats2half2_rn(v.z, v.w);
        ((__half2*)out)[2 * i]     = h0;
        ((__half2*)out)[2 * i + 1] = h1;
    }
}

// ---------------- fp16 mma.sync GEMM (R15 version, proven 297.1) ------------
// C[M, Ntot] = A[M, K] * B[Ntot, K]^T + bias.  A, B are fp16, C fp32.
#define GBM  128
#define PADH 40

template <int NT>
__global__ __launch_bounds__(256, 2)
void gemm_mma_f16(const __half* __restrict__ A, const __half* __restrict__ B,
                  const float* __restrict__ bias, float* __restrict__ C,
                  int Ntot, int K)
{
    constexpr int BN   = NT * 16;
    constexpr int ROWS = GBM + BN;
    constexpr int STGB = ROWS * PADH * 2;     // bytes per stage

    extern __shared__ char smc[];
    const uint32_t sbase = smem_u32(smc);

    const int tid  = threadIdx.x;
    const int lane = tid & 31;
    const int wid  = tid >> 5;
    const int warpM = wid & 3;
    const int warpN = wid >> 2;
    const int gid = lane >> 2;
    const int tig = lane & 3;

    const int m0 = blockIdx.y * GBM;
    const int n0 = blockIdx.x * BN;
    const int niter = K / 32;

    const __half* Ag = A + (size_t)m0 * K;
    const __half* Bg = B + (size_t)n0 * K;

    const int q    = lane >> 3;
    const int row8 = ((q & 1) << 3) + (lane & 7);
    const int kofB = (q >> 1) << 4;
    const uint32_t a_off = (uint32_t)((warpM * 32 + row8) * PADH * 2 + kofB);
    const uint32_t b_off = (uint32_t)((GBM + warpN * NT * 8 + row8) * PADH * 2 + kofB);

    float acc[2][NT][4];
#pragma unroll
    for (int mt = 0; mt < 2; mt++)
#pragma unroll
        for (int nt = 0; nt < NT; nt++)
#pragma unroll
            for (int z = 0; z < 4; z++) acc[mt][nt][z] = 0.f;

    auto issue = [&](int kt, int s) {
        if (kt < niter) {
            for (int c = tid; c < ROWS * 4; c += 256) {
                int row = c >> 2;
                int o8  = (c & 3) * 8;
                uint32_t dst = sbase + (uint32_t)(s * STGB + row * PADH * 2 + o8 * 2);
                const __half* src = (row < GBM)
                    ? Ag + (size_t)row * K + kt * 32 + o8
                    : Bg + (size_t)(row - GBM) * K + kt * 32 + o8;
                asm volatile("cp.async.cg.shared.global [%0], [%1], 16;"
                             :: "r"(dst), "l"(src) : "memory");
            }
        }
        asm volatile("cp.async.commit_group;" ::: "memory");
    };

    issue(0, 0);
    issue(1, 1);

    for (int it = 0; it < niter; it++) {
        asm volatile("cp.async.wait_group 1;" ::: "memory");
        __syncthreads();
        issue(it + 2, (it + 2) % 3);

        const uint32_t stg = sbase + (uint32_t)((it % 3) * STGB);
        const uint32_t aB = stg + a_off;
        const uint32_t bB = stg + b_off;

#pragma unroll
        for (int ks = 0; ks < 2; ks++) {
            const uint32_t kb = ks * 32;
            uint32_t afr[2][4];
            ldsm_x4(afr[0], aB + kb);
            ldsm_x4(afr[1], aB + kb + 16 * PADH * 2);
            uint32_t bfr[NT / 2][4];
#pragma unroll
            for (int p = 0; p < NT / 2; p++)
                ldsm_x4(bfr[p], bB + kb + (uint32_t)(p * 16 * PADH * 2));
#pragma unroll
            for (int mt = 0; mt < 2; mt++)
#pragma unroll
                for (int p = 0; p < NT / 2; p++) {
                    mma_f16(acc[mt][2 * p + 0], afr[mt], bfr[p][0], bfr[p][2]);
                    mma_f16(acc[mt][2 * p + 1], afr[mt], bfr[p][1], bfr[p][3]);
                }
        }
    }

#pragma unroll
    for (int mt = 0; mt < 2; mt++) {
        int row = m0 + warpM * 32 + mt * 16 + gid;
#pragma unroll
        for (int nt = 0; nt < NT; nt++) {
            int col = n0 + warpN * NT * 8 + nt * 8 + 2 * tig;
            float b0 = __ldg(&bias[col]);
            float b1 = __ldg(&bias[col + 1]);
            *(float2*)(C + (size_t)row * Ntot + col) =
                make_float2(acc[mt][nt][0] + b0, acc[mt][nt][1] + b1);
            *(float2*)(C + (size_t)(row + 8) * Ntot + col) =
                make_float2(acc[mt][nt][2] + b0, acc[mt][nt][3] + b1);
        }
    }
}

#define GEMM_SMEM_NT6 98304
#define GEMM_SMEM_NT8 ((GBM + 128) * PADH * 2 * 3)   // 61440

// ---------------- RoPE (standalone, frozen) ----------------
__global__ void rope_kernel(const float* __restrict__ cosT,
                            const float* __restrict__ sinT)
{
    const int t = blockIdx.x;
    float* row = g_qkv + (size_t)t * QKVC;
    const float* ct = cosT + t * 64;
    const float* st = sinT + t * 64;
    for (int p = threadIdx.x; p < 40 * 32; p += blockDim.x) {
        int hh = p >> 5;
        int dl = p & 31;
        int base = (hh < 32) ? hh * 64 : 2048 + (hh - 32) * 64;
        float lo = row[base + dl];
        float hi = row[base + dl + 32];
        float c0 = ct[dl],      s0 = st[dl];
        float c1 = ct[dl + 32], s1 = st[dl + 32];
        row[base + dl]      = lo * c0 - hi * s0;
        row[base + dl + 32] = hi * c1 + lo * s1;
    }
}

// ---------------- SWA v4: fp16 MMAs, fp32 score path ----------------
// Keys u in [0,160): global key j = t0 - 127 + u; valid u <= 142 && j >= 0.
// Qh/Kh/Vt fp16; S = Qh Kh^T in fp32 regs -> P32 (fp32) -> softmax ->
// exp written fp16 in-place at the head of each P32 row -> PV fp16.
#define QSTRH  72       // halves; 144 B (9 x 16B, odd)
#define KSTRH  72
#define VSTRH  168      // halves; 336 B (21 x 16B, odd)
#define PSTRF  164      // floats; 656 B (41 x 16B, odd)
#define NU     160
#define OFFB_Q   0
#define OFFB_K   9216                   // 64*144
#define OFFB_V   32256                  // + 160*144
#define OFFB_P   53760                  // + 64*336
#define OFFB_DEN 95744                  // + 64*656
#define SWA_SMEM (95744 + 256)          // 96000 B -> 2 CTAs/SM

__global__ __launch_bounds__(256, 2)
void swa_kernel(const float* __restrict__ sinks)
{
    extern __shared__ char smc[];
    const uint32_t sb = smem_u32(smc);
    const int tid = threadIdx.x, lane = tid & 31, wid = tid >> 5;
    const int gid = lane >> 2, tig = lane & 3;
    const int t0  = blockIdx.x * TQ;
    const int kvh = blockIdx.y;

    __half* Qh  = (__half*)(smc + OFFB_Q);
    __half* Kh  = (__half*)(smc + OFFB_K);
    __half* Vt  = (__half*)(smc + OFFB_V);
    float*  P32 = (float*)(smc + OFFB_P);
    float*  den = (float*)(smc + OFFB_DEN);

    // ---- load K[u][d] and Vt[d][u] as fp16 (zero outside band) ----
    for (int idx = tid; idx < NU * 64; idx += 256) {
        int u = idx >> 6, d = idx & 63;
        int j = t0 - 127 + u;
        float kv = 0.f, vv = 0.f;
        if (u <= 142 && j >= 0) {
            const float* r = g_qkv + (size_t)j * QKVC;
            kv = r[2048 + kvh * 64 + d];
            vv = r[2560 + kvh * 64 + d];
        }
        Kh[u * KSTRH + d] = __float2half(kv);
        Vt[d * VSTRH + u] = __float2half(vv);
    }
    // ---- load Q (scaled) fp16 ----
    for (int idx = tid; idx < 64 * 64; idx += 256) {
        int r = idx >> 6, d = idx & 63;
        int i = r >> 2, g = r & 3;
        Qh[r * QSTRH + d] = __float2half(
            g_qkv[(size_t)(t0 + i) * QKVC + (kvh * 4 + g) * 64 + d] * 0.125f);
    }
    __syncthreads();

    // ldmatrix per-lane constants (b16 native)
    const int q    = lane >> 3;
    const int row8 = ((q & 1) << 3) + (lane & 7);
    const int kofB = (q >> 1) << 4;     // 0 or 16 bytes

    // ---- QK (fp16): warp grid 4M x 2N; warp tile 16 x 80; K=64 (4 k16) ----
    {
        const int mrow = (wid & 3) << 4;
        const int ncol = (wid >> 2) * 80;
        float s[10][4];
#pragma unroll
        for (int nt = 0; nt < 10; nt++)
#pragma unroll
            for (int z = 0; z < 4; z++) s[nt][z] = 0.f;

        const uint32_t Qb = sb + (uint32_t)(OFFB_Q + (mrow + row8) * 144 + kofB);
        const uint32_t Kb = sb + (uint32_t)(OFFB_K + (ncol + row8) * 144 + kofB);
#pragma unroll
        for (int ks = 0; ks < 4; ks++) {
            const uint32_t kb = ks * 32;          // 16 halves
            uint32_t afr[4];
            ldsm_x4(afr, Qb + kb);
            uint32_t bfr[5][4];
#pragma unroll
            for (int p = 0; p < 5; p++)
                ldsm_x4(bfr[p], Kb + kb + (uint32_t)(p * 16 * 144));
#pragma unroll
            for (int p = 0; p < 5; p++) {
                mma_f16(s[2 * p + 0], afr, bfr[p][0], bfr[p][2]);
                mma_f16(s[2 * p + 1], afr, bfr[p][1], bfr[p][3]);
            }
        }
        // store fp32 scores
#pragma unroll
        for (int nt = 0; nt < 10; nt++) {
            int col = ncol + nt * 8 + 2 * tig;
            P32[(mrow + gid) * PSTRF + col]         = s[nt][0];
            P32[(mrow + gid) * PSTRF + col + 1]     = s[nt][1];
            P32[(mrow + gid + 8) * PSTRF + col]     = s[nt][2];
            P32[(mrow + gid + 8) * PSTRF + col + 1] = s[nt][3];
        }
    }
    __syncthreads();

    // ---- banded softmax; exp written fp16 in-place at row head ----
    {
        const int lim = 127 - t0;
        for (int rr = 0; rr < 8; rr++) {
            int r = wid * 8 + rr;
            int i = r >> 2, g = r & 3;
            int lo = (i > lim) ? i : lim;
            int hi = i + 127;
            float v[5];
#pragma unroll
            for (int c = 0; c < 5; c++) {
                int u = lane + c * 32;
                float x = P32[r * PSTRF + u];
                v[c] = (u >= lo && u <= hi) ? x : -1e30f;
            }
            float m = v[0];
#pragma unroll
            for (int c = 1; c < 5; c++) m = fmaxf(m, v[c]);
#pragma unroll
            for (int o = 16; o; o >>= 1)
                m = fmaxf(m, __shfl_xor_sync(0xffffffffu, m, o));
            float snk = __ldg(&sinks[kvh * 4 + g]);
            m = fmaxf(m, snk);
            float sum = 0.f;
            __half* Ph = (__half*)(P32 + r * PSTRF);   // row head, 656B stride
#pragma unroll
            for (int c = 0; c < 5; c++) {
                int u = lane + c * 32;
                __half he = __float2half(
                    (u >= lo && u <= hi) ? __expf(v[c] - m) : 0.f);
                Ph[u] = he;
                sum += __half2float(he);
            }
#pragma unroll
            for (int o = 16; o; o >>= 1)
                sum += __shfl_xor_sync(0xffffffffu, sum, o);
            sum += __expf(snk - m);
            if (lane == 0) den[r] = 1.0f / sum;
        }
    }
    __syncthreads();

    // ---- PV (fp16): warp tile 16 x 32; K = 160 (10 k16) ----
    {
        const int mrow = (wid & 3) << 4;
        const int ncol = (wid >> 2) << 5;
        float o[4][4];
#pragma unroll
        for (int nt = 0; nt < 4; nt++)
#pragma unroll
            for (int z = 0; z < 4; z++) o[nt][z] = 0.f;

        const uint32_t Pb = sb + (uint32_t)(OFFB_P + (mrow + row8) * 656 + kofB);
        const uint32_t Vb = sb + (uint32_t)(OFFB_V + (ncol + row8) * 336 + kofB);
#pragma unroll
        for (int ks = 0; ks < 10; ks++) {
            const uint32_t kb = ks * 32;
            uint32_t afr[4];
            ldsm_x4(afr, Pb + kb);
            uint32_t bfr[2][4];
            ldsm_x4(bfr[0], Vb + kb);
            ldsm_x4(bfr[1], Vb + kb + (uint32_t)(16 * 336));
#pragma unroll
            for (int p = 0; p < 2; p++) {
                mma_f16(o[2 * p + 0], afr, bfr[p][0], bfr[p][2]);
                mma_f16(o[2 * p + 1], afr, bfr[p][1], bfr[p][3]);
            }
        }
        int r0 = mrow + gid, r1 = r0 + 8;
        float i0 = den[r0], i1 = den[r1];
        int tA = t0 + (r0 >> 2), chA = (kvh * 4 + (r0 & 3)) * 64;
        int tB = t0 + (r1 >> 2), chB = (kvh * 4 + (r1 & 3)) * 64;
#pragma unroll
        for (int nt = 0; nt < 4; nt++) {
            int col = ncol + nt * 8 + 2 * tig;
            *(__half2*)(g_attn_h + (size_t)tA * DIMX + chA + col) =
                __floats2half2_rn(o[nt][0] * i0, o[nt][1] * i0);
            *(__half2*)(g_attn_h + (size_t)tB * DIMX + chB + col) =
                __floats2half2_rn(o[nt][2] * i1, o[nt][3] * i1);
        }
    }
}

// ---------------- host ----------------
extern "C" void kernel_launch(void* const* d_in, const int* in_sizes, int n_in,
                              void* d_out, int out_size)
{
    (void)in_sizes; (void)n_in; (void)out_size;
    const float* x     = (const float*)d_in[0];
    const float* cosT  = (const float*)d_in[1];
    const float* sinT  = (const float*)d_in[2];
    const float* Wqkv  = (const float*)d_in[3];
    const float* bqkv  = (const float*)d_in[4];
    const float* Wo    = (const float*)d_in[5];
    const float* bo    = (const float*)d_in[6];
    const float* sinks = (const float*)d_in[7];
    float* out = (float*)d_out;

    float*  qkv = nullptr;
    __half *xh = nullptr, *wqkvh = nullptr, *woh = nullptr, *attnh = nullptr;
    cudaGetSymbolAddress((void**)&qkv,   g_qkv);
    cudaGetSymbolAddress((void**)&xh,    g_xh);
    cudaGetSymbolAddress((void**)&wqkvh, g_wqkvh);
    cudaGetSymbolAddress((void**)&woh,   g_woh);
    cudaGetSymbolAddress((void**)&attnh, g_attn_h);

    cudaFuncSetAttribute((const void*)gemm_mma_f16<6>,
                         cudaFuncAttributeMaxDynamicSharedMemorySize, GEMM_SMEM_NT6);
    cudaFuncSetAttribute((const void*)gemm_mma_f16<8>,
                         cudaFuncAttributeMaxDynamicSharedMemorySize, GEMM_SMEM_NT8);
    cudaFuncSetAttribute(swa_kernel,
                         cudaFuncAttributeMaxDynamicSharedMemorySize, SWA_SMEM);

    // 0) fp32 -> fp16 pre-convert passes
    cvt_f16_kernel<<<(T_TOK * DIMX / 4 + 255) / 256, 256>>>(x,    xh,    T_TOK * DIMX / 4);
    cvt_f16_kernel<<<(QKVC * DIMX / 4 + 255) / 256, 256>>>(Wqkv, wqkvh, QKVC * DIMX / 4);
    cvt_f16_kernel<<<(DIMX * DIMX / 4 + 255) / 256, 256>>>(Wo,   woh,   DIMX * DIMX / 4);

    // 1) qkv = x @ Wqkv^T + bqkv  (fp16 mma, BN=96 -> 512 CTAs, 2 CTAs/SM)
    gemm_mma_f16<6><<<dim3(QKVC / 96, T_TOK / GBM), 256, GEMM_SMEM_NT6>>>(
        xh, wqkvh, bqkv, qkv, QKVC, DIMX);
    // 2) RoPE in-place on q,k (fp32)
    rope_kernel<<<T_TOK, 256>>>(cosT, sinT);
    // 3) fp16 sliding-window attention with sink (fp32 score path)
    swa_kernel<<<dim3(T_TOK / TQ, NKV), 256, SWA_SMEM>>>(sinks);
    // 4) out = attn @ Wo^T + bo   (fp16 mma, BN=128 -> 256 CTAs)
    gemm_mma_f16<8><<<dim3(DIMX / 128, T_TOK / GBM), 256, GEMM_SMEM_NT8>>>(
        attnh, woh, bo, out, DIMX, DIMX);
}